// round 2
// baseline (speedup 1.0000x reference)
#include <cuda_runtime.h>
#include <math.h>

#define BATCH 2
#define SEQ 1024
#define HID 4096
#define NH 32
#define NKV 2
#define HD 128
#define FFN 13696
#define QKV_DIM ((NH + 2*NKV)*HD)   // 4608
#define M_ROWS (BATCH*SEQ)          // 2048
#define EPSV 1e-5f
#define V_OFF ((NH+NKV)*HD)         // 4352
#define K_OFF (NH*HD)               // 4096

// ------------------------- scratch (device globals) -------------------------
__device__ float g_xnorm[M_ROWS * HID];          // 33.5 MB (also reused as attn_out)
__device__ float g_qkv[M_ROWS * QKV_DIM];        // 37.7 MB
__device__ float g_attn[M_ROWS * HID];           // 33.5 MB (attention ctx, later mlp_out)
__device__ float g_hidden[M_ROWS * HID];         // 33.5 MB
__device__ float g_y[M_ROWS * HID];              // 33.5 MB
__device__ float g_inter[M_ROWS * 2 * FFN];      // 224 MB
__device__ float g_gated[M_ROWS * FFN];          // 112 MB

// ------------------------- helpers -------------------------
__device__ __forceinline__ float warp_sum(float v) {
#pragma unroll
    for (int o = 16; o > 0; o >>= 1) v += __shfl_xor_sync(0xffffffffu, v, o);
    return v;
}

// ------------------------- fused (add+)rmsnorm -------------------------
// if res != nullptr: hid_out[row] = res+x (written), y = rmsnorm(res+x)*w
// else:              y = rmsnorm(x)*w
__global__ void __launch_bounds__(256) fused_norm_kernel(
    const float* __restrict__ res, const float* __restrict__ x,
    const float* __restrict__ w, float* __restrict__ hid_out,
    float* __restrict__ y)
{
    __shared__ __align__(16) float buf[HID];
    __shared__ float red[8];
    int row = blockIdx.x;
    size_t base = (size_t)row * HID;
    const float4* x4 = (const float4*)(x + base);
    const float4* r4 = res ? (const float4*)(res + base) : nullptr;
    float4* b4 = (float4*)buf;

    float ss = 0.f;
    for (int i = threadIdx.x; i < HID/4; i += 256) {
        float4 v = x4[i];
        if (r4) { float4 rr = r4[i]; v.x += rr.x; v.y += rr.y; v.z += rr.z; v.w += rr.w; }
        b4[i] = v;
        ss += v.x*v.x + v.y*v.y + v.z*v.z + v.w*v.w;
    }
    ss = warp_sum(ss);
    if ((threadIdx.x & 31) == 0) red[threadIdx.x >> 5] = ss;
    __syncthreads();
    float tot = 0.f;
#pragma unroll
    for (int i = 0; i < 8; i++) tot += red[i];
    float inv = rsqrtf(tot / (float)HID + EPSV);

    float4* y4 = (float4*)(y + base);
    float4* h4 = hid_out ? (float4*)(hid_out + base) : nullptr;
    const float4* w4 = (const float4*)w;
    for (int i = threadIdx.x; i < HID/4; i += 256) {
        float4 v = b4[i];
        if (h4) h4[i] = v;
        float4 ww = w4[i];
        float4 o;
        o.x = v.x * inv * ww.x; o.y = v.y * inv * ww.y;
        o.z = v.z * inv * ww.z; o.w = v.w * inv * ww.w;
        y4[i] = o;
    }
}

// ------------------------- SGEMM TN -------------------------
// C[M,N] = A[M,K] * B[N,K]^T (+bias[N]).  All of M,N %128==0, K %8==0.
template<bool HAS_BIAS>
__global__ void __launch_bounds__(256) sgemm_tn(
    const float* __restrict__ A, const float* __restrict__ Bw,
    const float* __restrict__ bias, float* __restrict__ C,
    int M, int N, int K)
{
    __shared__ __align__(16) float As[8][132];
    __shared__ __align__(16) float Bs[8][132];
    int tid = threadIdx.x;
    int bm = blockIdx.y * 128;
    int bn = blockIdx.x * 128;
    int lrow = tid >> 1;          // 0..127
    int lk4  = (tid & 1) << 2;    // 0 or 4
    const float* Aptr = A + (size_t)(bm + lrow) * K + lk4;
    const float* Bptr = Bw + (size_t)(bn + lrow) * K + lk4;
    int tx = tid & 15, ty = tid >> 4;

    float acc[8][8];
#pragma unroll
    for (int i = 0; i < 8; i++)
#pragma unroll
        for (int j = 0; j < 8; j++) acc[i][j] = 0.f;

    for (int k0 = 0; k0 < K; k0 += 8) {
        float4 a = *(const float4*)(Aptr + k0);
        float4 b = *(const float4*)(Bptr + k0);
        As[lk4+0][lrow] = a.x; As[lk4+1][lrow] = a.y;
        As[lk4+2][lrow] = a.z; As[lk4+3][lrow] = a.w;
        Bs[lk4+0][lrow] = b.x; Bs[lk4+1][lrow] = b.y;
        Bs[lk4+2][lrow] = b.z; Bs[lk4+3][lrow] = b.w;
        __syncthreads();
#pragma unroll
        for (int kk = 0; kk < 8; kk++) {
            float4 a0 = *(const float4*)&As[kk][ty*4];
            float4 a1 = *(const float4*)&As[kk][64 + ty*4];
            float4 b0 = *(const float4*)&Bs[kk][tx*4];
            float4 b1 = *(const float4*)&Bs[kk][64 + tx*4];
            float ar[8] = {a0.x,a0.y,a0.z,a0.w,a1.x,a1.y,a1.z,a1.w};
            float br[8] = {b0.x,b0.y,b0.z,b0.w,b1.x,b1.y,b1.z,b1.w};
#pragma unroll
            for (int i = 0; i < 8; i++)
#pragma unroll
                for (int j = 0; j < 8; j++)
                    acc[i][j] = fmaf(ar[i], br[j], acc[i][j]);
        }
        __syncthreads();
    }

    int c0 = bn + tx*4;
    int c1 = bn + 64 + tx*4;
    float4 bia0 = make_float4(0.f,0.f,0.f,0.f), bia1 = bia0;
    if (HAS_BIAS) {
        bia0 = *(const float4*)(bias + c0);
        bia1 = *(const float4*)(bias + c1);
    }
#pragma unroll
    for (int i = 0; i < 8; i++) {
        int row = bm + ((i < 4) ? (ty*4 + i) : (64 + ty*4 + (i - 4)));
        float* crow = C + (size_t)row * N;
        float4 v0 = make_float4(acc[i][0]+bia0.x, acc[i][1]+bia0.y,
                                acc[i][2]+bia0.z, acc[i][3]+bia0.w);
        float4 v1 = make_float4(acc[i][4]+bia1.x, acc[i][5]+bia1.y,
                                acc[i][6]+bia1.z, acc[i][7]+bia1.w);
        *(float4*)(crow + c0) = v0;
        *(float4*)(crow + c1) = v1;
    }
}

// ------------------------- RoPE (in-place on q,k of qkv) -------------------------
__global__ void rope_kernel(const int* __restrict__ positions, float* __restrict__ qkv)
{
    int bs = blockIdx.x;          // 0..2047  (b*S+s)
    int hh = blockIdx.y;          // 0..33 : q heads 0..31, k heads 32..33 (contiguous layout)
    int i  = threadIdx.x;         // 0..63
    float* base = qkv + (size_t)bs * QKV_DIM + hh * HD;
    float pos = (float)positions[bs];
    // inv_freq = 10000^(-i/64) = exp(-i * ln(10000)/64)
    float freq = __expf(-(float)i * 0.14391565217f);
    float ang = pos * freq;
    float sn, cs;
    sincosf(ang, &sn, &cs);
    float x1 = base[i];
    float x2 = base[i + 64];
    base[i]      = x1 * cs - x2 * sn;
    base[i + 64] = x2 * cs + x1 * sn;
}

// ------------------------- flash attention (causal, GQA) -------------------------
// grid: (S/32, NH, B), block 128. Each block: 32 query rows for one head.
__global__ void __launch_bounds__(128) flash_attn_kernel(
    const float* __restrict__ qkv, float* __restrict__ attn)
{
    __shared__ __align__(16) float Qs[32][HD];
    __shared__ __align__(16) float KVs[32][HD];
    __shared__ float Ss[32][33];
    __shared__ float m_s[32], l_s[32], alpha_s[32];

    int qt = blockIdx.x;
    int h  = blockIdx.y;
    int b  = blockIdx.z;
    int kvh = h >> 4;                 // NH/NKV = 16
    int tid = threadIdx.x;
    int r  = tid >> 2;                // query row within tile
    int qd = tid & 3;                 // dim quarter (32 floats)
    int q0 = qt * 32;

    // load Q tile
    for (int i = tid; i < 32*32; i += 128) {
        int row = i >> 5, c4 = i & 31;
        ((float4*)Qs[row])[c4] =
            *(const float4*)(qkv + (size_t)(b*SEQ + q0 + row) * QKV_DIM + h*HD + c4*4);
    }
    if (tid < 32) { m_s[tid] = -1e30f; l_s[tid] = 0.f; }
    float acc[32];
#pragma unroll
    for (int i = 0; i < 32; i++) acc[i] = 0.f;
    __syncthreads();

    const float scale = 0.08838834764831845f; // 1/sqrt(128)

    for (int kt = 0; kt <= qt; kt++) {
        int k0 = kt * 32;
        // load K tile
        for (int i = tid; i < 32*32; i += 128) {
            int row = i >> 5, c4 = i & 31;
            ((float4*)KVs[row])[c4] =
                *(const float4*)(qkv + (size_t)(b*SEQ + k0 + row) * QKV_DIM + K_OFF + kvh*HD + c4*4);
        }
        __syncthreads();

        // scores: thread computes 8 keys j0..j0+7 for its row r
        int j0 = qd * 8;
        float sc[8];
#pragma unroll
        for (int jj = 0; jj < 8; jj++) sc[jj] = 0.f;
        const float4* q4 = (const float4*)Qs[r];
#pragma unroll 4
        for (int d4 = 0; d4 < 32; d4++) {
            float4 qv = q4[d4];
#pragma unroll
            for (int jj = 0; jj < 8; jj++) {
                float4 kv = ((const float4*)KVs[j0 + jj])[d4];
                sc[jj] += qv.x*kv.x + qv.y*kv.y + qv.z*kv.z + qv.w*kv.w;
            }
        }
#pragma unroll
        for (int jj = 0; jj < 8; jj++) {
            int kg = k0 + j0 + jj;
            Ss[r][j0 + jj] = (kg <= q0 + r) ? sc[jj] * scale : -1e30f;
        }
        __syncthreads();

        // online softmax per row (one thread per row)
        if (tid < 32) {
            float mx = m_s[tid];
            float tm = -1e30f;
#pragma unroll 8
            for (int j = 0; j < 32; j++) tm = fmaxf(tm, Ss[tid][j]);
            float mn = fmaxf(mx, tm);
            float al = __expf(mx - mn);
            float sum = 0.f;
#pragma unroll 8
            for (int j = 0; j < 32; j++) {
                float p = __expf(Ss[tid][j] - mn);
                Ss[tid][j] = p;
                sum += p;
            }
            m_s[tid] = mn;
            l_s[tid] = l_s[tid] * al + sum;
            alpha_s[tid] = al;
        }
        // load V tile into same buffer (K already consumed)
        for (int i = tid; i < 32*32; i += 128) {
            int row = i >> 5, c4 = i & 31;
            ((float4*)KVs[row])[c4] =
                *(const float4*)(qkv + (size_t)(b*SEQ + k0 + row) * QKV_DIM + V_OFF + kvh*HD + c4*4);
        }
        __syncthreads();

        // rescale + P@V
        float al = alpha_s[r];
#pragma unroll
        for (int i = 0; i < 32; i++) acc[i] *= al;
#pragma unroll 4
        for (int j = 0; j < 32; j++) {
            float p = Ss[r][j];
            const float4* v4 = (const float4*)&KVs[j][qd*32];
#pragma unroll
            for (int i4 = 0; i4 < 8; i4++) {
                float4 vv = v4[i4];
                acc[i4*4+0] = fmaf(p, vv.x, acc[i4*4+0]);
                acc[i4*4+1] = fmaf(p, vv.y, acc[i4*4+1]);
                acc[i4*4+2] = fmaf(p, vv.z, acc[i4*4+2]);
                acc[i4*4+3] = fmaf(p, vv.w, acc[i4*4+3]);
            }
        }
        __syncthreads();
    }

    float invl = 1.f / l_s[r];
    float4* o4 = (float4*)(attn + (size_t)(b*SEQ + q0 + r) * HID + h*HD + qd*32);
#pragma unroll
    for (int i4 = 0; i4 < 8; i4++) {
        float4 o;
        o.x = acc[i4*4+0] * invl; o.y = acc[i4*4+1] * invl;
        o.z = acc[i4*4+2] * invl; o.w = acc[i4*4+3] * invl;
        o4[i4] = o;
    }
}

// ------------------------- SwiGLU -------------------------
__global__ void swiglu_kernel(const float* __restrict__ inter, float* __restrict__ gated)
{
    int idx = blockIdx.x * blockDim.x + threadIdx.x;
    if (idx >= M_ROWS * FFN) return;
    int row = idx / FFN;
    int f   = idx - row * FFN;
    const float* irow = inter + (size_t)row * (2*FFN);
    float a = irow[f];
    float b = irow[FFN + f];
    float s = a / (1.f + __expf(-a));
    gated[idx] = s * b;
}

// ------------------------- elementwise add -------------------------
__global__ void add_kernel(const float* __restrict__ a, const float* __restrict__ b,
                           float* __restrict__ out, int n4)
{
    int i = blockIdx.x * blockDim.x + threadIdx.x;
    if (i >= n4) return;
    float4 va = ((const float4*)a)[i];
    float4 vb = ((const float4*)b)[i];
    float4 o;
    o.x = va.x + vb.x; o.y = va.y + vb.y; o.z = va.z + vb.z; o.w = va.w + vb.w;
    ((float4*)out)[i] = o;
}

// ------------------------- launch -------------------------
extern "C" void kernel_launch(void* const* d_in, const int* in_sizes, int n_in,
                              void* d_out, int out_size)
{
    const int*   positions = (const int*)d_in[0];
    const float* hs        = (const float*)d_in[1];
    const float* ln1       = (const float*)d_in[2];
    const float* wqkv      = (const float*)d_in[3];
    const float* bqkv      = (const float*)d_in[4];
    const float* wo        = (const float*)d_in[5];
    const float* ln2       = (const float*)d_in[6];
    const float* w14       = (const float*)d_in[7];
    const float* w41       = (const float*)d_in[8];
    float* out = (float*)d_out;

    float *xnorm, *qkv, *attn, *hidden, *y, *inter, *gated;
    cudaGetSymbolAddress((void**)&xnorm,  g_xnorm);
    cudaGetSymbolAddress((void**)&qkv,    g_qkv);
    cudaGetSymbolAddress((void**)&attn,   g_attn);
    cudaGetSymbolAddress((void**)&hidden, g_hidden);
    cudaGetSymbolAddress((void**)&y,      g_y);
    cudaGetSymbolAddress((void**)&inter,  g_inter);
    cudaGetSymbolAddress((void**)&gated,  g_gated);

    // 1) x = rmsnorm(hidden_states) * ln1_w
    fused_norm_kernel<<<M_ROWS, 256>>>(nullptr, hs, ln1, nullptr, xnorm);

    // 2) qkv = x @ wqkv^T + bqkv
    sgemm_tn<true><<<dim3(QKV_DIM/128, M_ROWS/128), 256>>>(xnorm, wqkv, bqkv, qkv,
                                                           M_ROWS, QKV_DIM, HID);
    // 3) rope on q,k
    rope_kernel<<<dim3(M_ROWS, NH + NKV), 64>>>(positions, qkv);

    // 4) attention -> attn (context, [B,S,H])
    flash_attn_kernel<<<dim3(SEQ/32, NH, BATCH), 128>>>(qkv, attn);

    // 5) attn_out = attn @ wo^T   (reuse xnorm buffer)
    sgemm_tn<false><<<dim3(HID/128, M_ROWS/128), 256>>>(attn, wo, nullptr, xnorm,
                                                        M_ROWS, HID, HID);
    // 6) hidden = hs + attn_out ; y = rmsnorm(hidden) * ln2_w
    fused_norm_kernel<<<M_ROWS, 256>>>(hs, xnorm, ln2, hidden, y);

    // 7) inter = y @ w14^T  [M, 2*FFN]
    sgemm_tn<false><<<dim3((2*FFN)/128, M_ROWS/128), 256>>>(y, w14, nullptr, inter,
                                                            M_ROWS, 2*FFN, HID);
    // 8) gated = silu(a)*b
    swiglu_kernel<<<(M_ROWS*FFN + 255)/256, 256>>>(inter, gated);

    // 9) mlp_out = gated @ w41^T  (reuse attn buffer)
    sgemm_tn<false><<<dim3(HID/128, M_ROWS/128), 256>>>(gated, w41, nullptr, attn,
                                                        M_ROWS, HID, FFN);
    // 10) out = hidden + mlp_out
    add_kernel<<<(M_ROWS*HID/4 + 255)/256, 256>>>(hidden, attn, out, M_ROWS*HID/4);
}

// round 4
// speedup vs baseline: 1.9935x; 1.9935x over previous
#include <cuda_runtime.h>
#include <cuda_bf16.h>
#include <math.h>
#include <stdint.h>

#define BATCH 2
#define SEQ 1024
#define HID 4096
#define NH 32
#define NKV 2
#define HD 128
#define FFN 13696
#define QKV_DIM ((NH + 2*NKV)*HD)   // 4608
#define M_ROWS (BATCH*SEQ)          // 2048
#define EPSV 1e-5f
#define V_OFF ((NH+NKV)*HD)         // 4352
#define K_OFF (NH*HD)               // 4096
#define K2H (2*HID)                 // planar split row length for K=4096
#define K2F (2*FFN)                 // planar split row length for K=13696

// ------------------------- scratch (device globals) -------------------------
__device__ float g_qkv[(size_t)M_ROWS * QKV_DIM];
__device__ float g_attnout[(size_t)M_ROWS * HID];
__device__ float g_hidden[(size_t)M_ROWS * HID];
__device__ float g_inter[(size_t)M_ROWS * 2 * FFN];
__device__ float g_mlp[(size_t)M_ROWS * HID];
// planar split-bf16: each row = [hi(K) | lo(K)]
__device__ __nv_bfloat16 g_wqkv2[(size_t)QKV_DIM * K2H];
__device__ __nv_bfloat16 g_wo2[(size_t)HID * K2H];
__device__ __nv_bfloat16 g_w14b[(size_t)(2*FFN) * K2H];
__device__ __nv_bfloat16 g_w41b[(size_t)HID * K2F];
__device__ __nv_bfloat16 g_x2[(size_t)M_ROWS * K2H];
__device__ __nv_bfloat16 g_a2[(size_t)M_ROWS * K2H];
__device__ __nv_bfloat16 g_y2[(size_t)M_ROWS * K2H];
__device__ __nv_bfloat16 g_g2[(size_t)M_ROWS * K2F];

// ------------------------- PTX helpers -------------------------
__device__ __forceinline__ uint32_t smem_u32(const void* p) {
    uint32_t a;
    asm("{ .reg .u64 t; cvta.to.shared.u64 t, %1; cvt.u32.u64 %0, t; }" : "=r"(a) : "l"(p));
    return a;
}
__device__ __forceinline__ void cp16(uint32_t s, const void* g) {
    asm volatile("cp.async.cg.shared.global [%0], [%1], 16;" :: "r"(s), "l"(g));
}
__device__ __forceinline__ void ldsm4(uint32_t* r, uint32_t addr) {
    asm volatile("ldmatrix.sync.aligned.m8n8.x4.shared.b16 {%0,%1,%2,%3}, [%4];"
                 : "=r"(r[0]), "=r"(r[1]), "=r"(r[2]), "=r"(r[3]) : "r"(addr));
}
__device__ __forceinline__ void mma16816(float* c, const uint32_t* a, uint32_t b0, uint32_t b1) {
    asm volatile(
        "mma.sync.aligned.m16n8k16.row.col.f32.bf16.bf16.f32 "
        "{%0,%1,%2,%3}, {%4,%5,%6,%7}, {%8,%9}, {%0,%1,%2,%3};"
        : "+f"(c[0]), "+f"(c[1]), "+f"(c[2]), "+f"(c[3])
        : "r"(a[0]), "r"(a[1]), "r"(a[2]), "r"(a[3]), "r"(b0), "r"(b1));
}

// ------------------------- misc helpers -------------------------
__device__ __forceinline__ float warp_sum(float v) {
#pragma unroll
    for (int o = 16; o > 0; o >>= 1) v += __shfl_xor_sync(0xffffffffu, v, o);
    return v;
}
// split float4 -> 4 hi bf16 (uint2) + 4 lo bf16 (uint2)
__device__ __forceinline__ void split4p(float4 v, uint2& hi, uint2& lo) {
    union { uint2 u; __nv_bfloat16 h[4]; } H, L;
    float f[4] = {v.x, v.y, v.z, v.w};
#pragma unroll
    for (int k = 0; k < 4; k++) {
        __nv_bfloat16 h = __float2bfloat16(f[k]);
        H.h[k] = h;
        L.h[k] = __float2bfloat16(f[k] - __bfloat162float(h));
    }
    hi = H.u; lo = L.u;
}

// ------------------------- fp32 -> planar split-bf16 (weights) -------------------------
// in: flat [N*K] fp32 (rows of length K). out: rows of length 2K: [hi | lo].
// kq = K/4 (float4 units per row)
__global__ void split_planar_kernel(const float* __restrict__ in,
                                    __nv_bfloat16* __restrict__ out,
                                    long long n4, int kq) {
    long long i = (long long)blockIdx.x * blockDim.x + threadIdx.x;
    if (i >= n4) return;
    float4 v = ((const float4*)in)[i];
    uint2 hi, lo;
    split4p(v, hi, lo);
    long long n = i / kq;
    long long hidx = i + n * kq;      // n*2K/4 + k4
    ((uint2*)out)[hidx] = hi;
    ((uint2*)out)[hidx + kq] = lo;
}

// ------------------------- fused (add+)rmsnorm, planar split output -------------------------
__global__ void __launch_bounds__(256) fused_norm_kernel(
    const float* __restrict__ res, const float* __restrict__ x,
    const float* __restrict__ w, float* __restrict__ hid_out,
    __nv_bfloat16* __restrict__ y2) {
    __shared__ __align__(16) float buf[HID];
    __shared__ float red[8];
    int row = blockIdx.x;
    size_t base = (size_t)row * HID;
    const float4* x4 = (const float4*)(x + base);
    const float4* r4 = res ? (const float4*)(res + base) : nullptr;
    float4* b4 = (float4*)buf;

    float ss = 0.f;
    for (int i = threadIdx.x; i < HID/4; i += 256) {
        float4 v = x4[i];
        if (r4) { float4 rr = r4[i]; v.x += rr.x; v.y += rr.y; v.z += rr.z; v.w += rr.w; }
        b4[i] = v;
        ss += v.x*v.x + v.y*v.y + v.z*v.z + v.w*v.w;
    }
    ss = warp_sum(ss);
    if ((threadIdx.x & 31) == 0) red[threadIdx.x >> 5] = ss;
    __syncthreads();
    float tot = 0.f;
#pragma unroll
    for (int i = 0; i < 8; i++) tot += red[i];
    float inv = rsqrtf(tot / (float)HID + EPSV);

    uint2* yh = (uint2*)(y2 + (size_t)row * K2H);
    uint2* yl = (uint2*)(y2 + (size_t)row * K2H + HID);
    float4* h4 = hid_out ? (float4*)(hid_out + base) : nullptr;
    const float4* w4 = (const float4*)w;
    for (int i = threadIdx.x; i < HID/4; i += 256) {
        float4 v = b4[i];
        if (h4) h4[i] = v;
        float4 ww = w4[i];
        float4 o;
        o.x = v.x * inv * ww.x; o.y = v.y * inv * ww.y;
        o.z = v.z * inv * ww.z; o.w = v.w * inv * ww.w;
        uint2 hi, lo;
        split4p(o, hi, lo);
        yh[i] = hi; yl[i] = lo;
    }
}

// ------------------------- split-bf16 HMMA GEMM -------------------------
// C[M=2048, N] = A * B^T where A2[M,2K]=[hi|lo], B2[N,2K]=[hi|lo].
// 3 K-phases: hiA*hiB, hiA*loB, loA*hiB. Tile 128x128, chunk 64.
#define NSTAGE 3
#define STAGE_BYTES 32768
#define GEMM_SMEM (NSTAGE * STAGE_BYTES + 1024)

__global__ void __launch_bounds__(256, 1) gemm_bf16(
    const __nv_bfloat16* __restrict__ A, const __nv_bfloat16* __restrict__ B,
    const float* __restrict__ bias, float* __restrict__ C,
    int NT, int Kel, int N) {
    extern __shared__ char smem[];
    uint32_t dataA = (smem_u32(smem) + 1023) & ~1023u;
    int tid = threadIdx.x;
    int wid = tid >> 5, lane = tid & 31;

    // supertile rasterization: 16 m-tiles x 18 n-tiles
    int g = blockIdx.x / (16*18);
    int r = blockIdx.x % (16*18);
    int gn = NT - g*18; if (gn > 18) gn = 18;
    int bn = (g*18 + r % gn) * 128;
    int bm = (r / gn) * 128;

    const size_t rowb = (size_t)Kel * 4;   // bytes per planar row (2K bf16)
    const char* Abase = (const char*)A + (size_t)bm * rowb;
    const char* Bbase = (const char*)B + (size_t)bn * rowb;
    const int KC = Kel >> 6;
    const int NC = 3 * KC;
    const int c16 = (tid & 7) * 16;
    const int row0 = tid >> 3;

    auto load_chunk = [&](int j) {
        int phase = (j >= 2*KC) ? 2 : (j >= KC ? 1 : 0);
        int jj = j - phase*KC;
        size_t a_byte = ((size_t)(phase == 2 ? Kel : 0) + (size_t)jj*64) * 2 + c16;
        size_t b_byte = ((size_t)(phase == 1 ? Kel : 0) + (size_t)jj*64) * 2 + c16;
        int s = j % NSTAGE;
        uint32_t sA = dataA + s*STAGE_BYTES;
        uint32_t sB = sA + 16384;
#pragma unroll
        for (int p = 0; p < 4; p++) {
            int row = row0 + p*32;
            uint32_t sw = row*128 + (c16 ^ ((row & 7) << 4));
            cp16(sA + sw, Abase + (size_t)row * rowb + a_byte);
            cp16(sB + sw, Bbase + (size_t)row * rowb + b_byte);
        }
        asm volatile("cp.async.commit_group;" ::: "memory");
    };

    float acc[4][4][4];
#pragma unroll
    for (int a = 0; a < 4; a++)
#pragma unroll
        for (int b = 0; b < 4; b++)
#pragma unroll
            for (int c = 0; c < 4; c++) acc[a][b][c] = 0.f;

    const int warp_m = (wid & 1) * 64;
    const int warp_n = (wid >> 1) * 32;

    load_chunk(0);
    load_chunk(1);

    for (int i = 0; i < NC; i++) {
        if (i + 2 < NC) load_chunk(i + 2);
        else asm volatile("cp.async.commit_group;" ::: "memory");
        asm volatile("cp.async.wait_group 2;" ::: "memory");
        __syncthreads();

        uint32_t sA = dataA + (i % NSTAGE)*STAGE_BYTES;
        uint32_t sB = sA + 16384;
#pragma unroll
        for (int ks = 0; ks < 4; ks++) {
            int kb = ks * 32;  // byte offset of k-step within 128B row
            uint32_t af[4][4];
#pragma unroll
            for (int mt = 0; mt < 4; mt++) {
                int rw = warp_m + mt*16 + (lane & 15);
                int cb = kb + ((lane >> 4) << 4);
                ldsm4(af[mt], sA + rw*128 + (cb ^ ((rw & 7) << 4)));
            }
            uint32_t bf[2][4];
#pragma unroll
            for (int nt = 0; nt < 2; nt++) {
                int nr = warp_n + nt*16 + ((lane >> 4) << 3) + (lane & 7);
                int cb = kb + (((lane >> 3) & 1) << 4);
                ldsm4(bf[nt], sB + nr*128 + (cb ^ ((nr & 7) << 4)));
            }
#pragma unroll
            for (int mt = 0; mt < 4; mt++) {
#pragma unroll
                for (int nj = 0; nj < 4; nj++) {
                    const uint32_t* bb = bf[nj >> 1];
                    uint32_t b0 = (nj & 1) ? bb[2] : bb[0];
                    uint32_t b1 = (nj & 1) ? bb[3] : bb[1];
                    mma16816(acc[mt][nj], af[mt], b0, b1);
                }
            }
        }
        __syncthreads();
    }

    // epilogue
#pragma unroll
    for (int mt = 0; mt < 4; mt++) {
        int row0g = bm + warp_m + mt*16 + (lane >> 2);
#pragma unroll
        for (int nj = 0; nj < 4; nj++) {
            int col = bn + warp_n + nj*8 + (lane & 3)*2;
            float b0 = 0.f, b1 = 0.f;
            if (bias) { b0 = bias[col]; b1 = bias[col+1]; }
            float* p0 = C + (size_t)row0g * N + col;
            float* p1 = C + (size_t)(row0g + 8) * N + col;
            *(float2*)p0 = make_float2(acc[mt][nj][0] + b0, acc[mt][nj][1] + b1);
            *(float2*)p1 = make_float2(acc[mt][nj][2] + b0, acc[mt][nj][3] + b1);
        }
    }
}

// ------------------------- RoPE (in-place on q,k of qkv) -------------------------
__global__ void rope_kernel(const int* __restrict__ positions, float* __restrict__ qkv) {
    int bs = blockIdx.x;
    int hh = blockIdx.y;
    int i  = threadIdx.x;
    float* base = qkv + (size_t)bs * QKV_DIM + hh * HD;
    float pos = (float)positions[bs];
    float freq = __expf(-(float)i * 0.14391565217f);
    float ang = pos * freq;
    float sn, cs;
    sincosf(ang, &sn, &cs);
    float x1 = base[i];
    float x2 = base[i + 64];
    base[i]      = x1 * cs - x2 * sn;
    base[i + 64] = x2 * cs + x1 * sn;
}

// ------------------------- flash attention (causal, GQA), planar split ctx out ----
__global__ void __launch_bounds__(128) flash_attn_kernel(
    const float* __restrict__ qkv, __nv_bfloat16* __restrict__ a2) {
    __shared__ __align__(16) float Qs[32][HD];
    __shared__ __align__(16) float KVs[32][HD];
    __shared__ float Ss[32][33];
    __shared__ float m_s[32], l_s[32], alpha_s[32];

    int qt = blockIdx.x;
    int h  = blockIdx.y;
    int b  = blockIdx.z;
    int kvh = h >> 4;
    int tid = threadIdx.x;
    int r  = tid >> 2;
    int qd = tid & 3;
    int q0 = qt * 32;

    for (int i = tid; i < 32*32; i += 128) {
        int row = i >> 5, c4 = i & 31;
        ((float4*)Qs[row])[c4] =
            *(const float4*)(qkv + (size_t)(b*SEQ + q0 + row) * QKV_DIM + h*HD + c4*4);
    }
    if (tid < 32) { m_s[tid] = -1e30f; l_s[tid] = 0.f; }
    float acc[32];
#pragma unroll
    for (int i = 0; i < 32; i++) acc[i] = 0.f;
    __syncthreads();

    const float scale = 0.08838834764831845f;

    for (int kt = 0; kt <= qt; kt++) {
        int k0 = kt * 32;
        for (int i = tid; i < 32*32; i += 128) {
            int row = i >> 5, c4 = i & 31;
            ((float4*)KVs[row])[c4] =
                *(const float4*)(qkv + (size_t)(b*SEQ + k0 + row) * QKV_DIM + K_OFF + kvh*HD + c4*4);
        }
        __syncthreads();

        int j0 = qd * 8;
        float sc[8];
#pragma unroll
        for (int jj = 0; jj < 8; jj++) sc[jj] = 0.f;
        const float4* q4 = (const float4*)Qs[r];
#pragma unroll 4
        for (int d4 = 0; d4 < 32; d4++) {
            float4 qv = q4[d4];
#pragma unroll
            for (int jj = 0; jj < 8; jj++) {
                float4 kv = ((const float4*)KVs[j0 + jj])[d4];
                sc[jj] += qv.x*kv.x + qv.y*kv.y + qv.z*kv.z + qv.w*kv.w;
            }
        }
#pragma unroll
        for (int jj = 0; jj < 8; jj++) {
            int kg = k0 + j0 + jj;
            Ss[r][j0 + jj] = (kg <= q0 + r) ? sc[jj] * scale : -1e30f;
        }
        __syncthreads();

        if (tid < 32) {
            float mx = m_s[tid];
            float tm = -1e30f;
#pragma unroll 8
            for (int j = 0; j < 32; j++) tm = fmaxf(tm, Ss[tid][j]);
            float mn = fmaxf(mx, tm);
            float al = __expf(mx - mn);
            float sum = 0.f;
#pragma unroll 8
            for (int j = 0; j < 32; j++) {
                float p = __expf(Ss[tid][j] - mn);
                Ss[tid][j] = p;
                sum += p;
            }
            m_s[tid] = mn;
            l_s[tid] = l_s[tid] * al + sum;
            alpha_s[tid] = al;
        }
        for (int i = tid; i < 32*32; i += 128) {
            int row = i >> 5, c4 = i & 31;
            ((float4*)KVs[row])[c4] =
                *(const float4*)(qkv + (size_t)(b*SEQ + k0 + row) * QKV_DIM + V_OFF + kvh*HD + c4*4);
        }
        __syncthreads();

        float al = alpha_s[r];
#pragma unroll
        for (int i = 0; i < 32; i++) acc[i] *= al;
#pragma unroll 4
        for (int j = 0; j < 32; j++) {
            float p = Ss[r][j];
            const float4* v4 = (const float4*)&KVs[j][qd*32];
#pragma unroll
            for (int i4 = 0; i4 < 8; i4++) {
                float4 vv = v4[i4];
                acc[i4*4+0] = fmaf(p, vv.x, acc[i4*4+0]);
                acc[i4*4+1] = fmaf(p, vv.y, acc[i4*4+1]);
                acc[i4*4+2] = fmaf(p, vv.z, acc[i4*4+2]);
                acc[i4*4+3] = fmaf(p, vv.w, acc[i4*4+3]);
            }
        }
        __syncthreads();
    }

    float invl = 1.f / l_s[r];
    size_t rbase = (size_t)(b*SEQ + q0 + r) * K2H;
    uint2* oh = (uint2*)(a2 + rbase + h*HD + qd*32);
    uint2* ol = (uint2*)(a2 + rbase + HID + h*HD + qd*32);
#pragma unroll
    for (int i4 = 0; i4 < 8; i4++) {
        float4 o = make_float4(acc[i4*4+0]*invl, acc[i4*4+1]*invl,
                               acc[i4*4+2]*invl, acc[i4*4+3]*invl);
        uint2 hi, lo;
        split4p(o, hi, lo);
        oh[i4] = hi; ol[i4] = lo;
    }
}

// ------------------------- SwiGLU + planar split -------------------------
__global__ void swiglu_split_kernel(const float* __restrict__ inter,
                                    __nv_bfloat16* __restrict__ g2) {
    int t = blockIdx.x * blockDim.x + threadIdx.x;
    if (t >= M_ROWS * (FFN/4)) return;
    int row = t / (FFN/4);
    int f4  = t - row * (FFN/4);
    const float* irow = inter + (size_t)row * (2*FFN);
    float4 a = *(const float4*)(irow + f4*4);
    float4 b = *(const float4*)(irow + FFN + f4*4);
    float4 o;
    o.x = (a.x / (1.f + __expf(-a.x))) * b.x;
    o.y = (a.y / (1.f + __expf(-a.y))) * b.y;
    o.z = (a.z / (1.f + __expf(-a.z))) * b.z;
    o.w = (a.w / (1.f + __expf(-a.w))) * b.w;
    uint2 hi, lo;
    split4p(o, hi, lo);
    size_t rbase = (size_t)row * K2F;
    *(uint2*)(g2 + rbase + f4*4) = hi;
    *(uint2*)(g2 + rbase + FFN + f4*4) = lo;
}

// ------------------------- elementwise add -------------------------
__global__ void add_kernel(const float* __restrict__ a, const float* __restrict__ b,
                           float* __restrict__ out, int n4) {
    int i = blockIdx.x * blockDim.x + threadIdx.x;
    if (i >= n4) return;
    float4 va = ((const float4*)a)[i];
    float4 vb = ((const float4*)b)[i];
    ((float4*)out)[i] = make_float4(va.x+vb.x, va.y+vb.y, va.z+vb.z, va.w+vb.w);
}

// ------------------------- launch -------------------------
extern "C" void kernel_launch(void* const* d_in, const int* in_sizes, int n_in,
                              void* d_out, int out_size) {
    const int*   positions = (const int*)d_in[0];
    const float* hs        = (const float*)d_in[1];
    const float* ln1       = (const float*)d_in[2];
    const float* wqkv      = (const float*)d_in[3];
    const float* bqkv      = (const float*)d_in[4];
    const float* wo        = (const float*)d_in[5];
    const float* ln2       = (const float*)d_in[6];
    const float* w14       = (const float*)d_in[7];
    const float* w41       = (const float*)d_in[8];
    float* out = (float*)d_out;

    float *qkv, *attnout, *hidden, *inter, *mlp;
    __nv_bfloat16 *wqkv2, *wo2, *w14b, *w41b, *x2, *a2, *y2, *g2;
    cudaGetSymbolAddress((void**)&qkv,     g_qkv);
    cudaGetSymbolAddress((void**)&attnout, g_attnout);
    cudaGetSymbolAddress((void**)&hidden,  g_hidden);
    cudaGetSymbolAddress((void**)&inter,   g_inter);
    cudaGetSymbolAddress((void**)&mlp,     g_mlp);
    cudaGetSymbolAddress((void**)&wqkv2,   g_wqkv2);
    cudaGetSymbolAddress((void**)&wo2,     g_wo2);
    cudaGetSymbolAddress((void**)&w14b,    g_w14b);
    cudaGetSymbolAddress((void**)&w41b,    g_w41b);
    cudaGetSymbolAddress((void**)&x2,      g_x2);
    cudaGetSymbolAddress((void**)&a2,      g_a2);
    cudaGetSymbolAddress((void**)&y2,      g_y2);
    cudaGetSymbolAddress((void**)&g2,      g_g2);

    cudaFuncSetAttribute(gemm_bf16, cudaFuncAttributeMaxDynamicSharedMemorySize, GEMM_SMEM);

    // weight splits (planar)
    {
        long long n4;
        n4 = (long long)QKV_DIM * HID / 4;
        split_planar_kernel<<<(unsigned)((n4+255)/256), 256>>>(wqkv, wqkv2, n4, HID/4);
        n4 = (long long)HID * HID / 4;
        split_planar_kernel<<<(unsigned)((n4+255)/256), 256>>>(wo, wo2, n4, HID/4);
        n4 = (long long)(2*FFN) * HID / 4;
        split_planar_kernel<<<(unsigned)((n4+255)/256), 256>>>(w14, w14b, n4, HID/4);
        n4 = (long long)HID * FFN / 4;
        split_planar_kernel<<<(unsigned)((n4+255)/256), 256>>>(w41, w41b, n4, FFN/4);
    }

    // 1) x2 = split(rmsnorm(hs) * ln1)
    fused_norm_kernel<<<M_ROWS, 256>>>(nullptr, hs, ln1, nullptr, x2);

    // 2) qkv = x @ wqkv^T + bqkv
    gemm_bf16<<<16*36, 256, GEMM_SMEM>>>(x2, wqkv2, bqkv, qkv, 36, HID, QKV_DIM);

    // 3) rope on q,k
    rope_kernel<<<dim3(M_ROWS, NH + NKV), 64>>>(positions, qkv);

    // 4) attention -> a2 (planar split ctx)
    flash_attn_kernel<<<dim3(SEQ/32, NH, BATCH), 128>>>(qkv, a2);

    // 5) attn_out = ctx @ wo^T
    gemm_bf16<<<16*32, 256, GEMM_SMEM>>>(a2, wo2, nullptr, attnout, 32, HID, HID);

    // 6) hidden = hs + attn_out ; y2 = split(rmsnorm(hidden) * ln2)
    fused_norm_kernel<<<M_ROWS, 256>>>(hs, attnout, ln2, hidden, y2);

    // 7) inter = y @ w14^T
    gemm_bf16<<<16*214, 256, GEMM_SMEM>>>(y2, w14b, nullptr, inter, 214, HID, 2*FFN);

    // 8) g2 = split(silu(a)*b)
    swiglu_split_kernel<<<(M_ROWS*(FFN/4) + 255)/256, 256>>>(inter, g2);

    // 9) mlp = gated @ w41^T
    gemm_bf16<<<16*32, 256, GEMM_SMEM>>>(g2, w41b, nullptr, mlp, 32, FFN, HID);

    // 10) out = hidden + mlp
    add_kernel<<<(M_ROWS*HID/4 + 255)/256, 256>>>(hidden, mlp, out, M_ROWS*HID/4);
}

// round 5
// speedup vs baseline: 2.2583x; 1.1328x over previous
#include <cuda_runtime.h>
#include <cuda_bf16.h>
#include <math.h>
#include <stdint.h>

#define BATCH 2
#define SEQ 1024
#define HID 4096
#define NH 32
#define NKV 2
#define HD 128
#define FFN 13696
#define QKV_DIM ((NH + 2*NKV)*HD)   // 4608
#define M_ROWS (BATCH*SEQ)          // 2048
#define EPSV 1e-5f
#define V_OFF ((NH+NKV)*HD)         // 4352
#define K_OFF (NH*HD)               // 4096
#define K2H (2*HID)                 // planar split row length for K=4096
#define K2F (2*FFN)                 // planar split row length for K=13696

// ------------------------- scratch (device globals) -------------------------
__device__ float g_qkv[(size_t)M_ROWS * QKV_DIM];
__device__ float g_attnout[(size_t)M_ROWS * HID];
__device__ float g_hidden[(size_t)M_ROWS * HID];
__device__ float g_inter[(size_t)M_ROWS * 2 * FFN];
// planar split-bf16: each row = [hi(K) | lo(K)]
__device__ __nv_bfloat16 g_wqkv2[(size_t)QKV_DIM * K2H];
__device__ __nv_bfloat16 g_wo2[(size_t)HID * K2H];
__device__ __nv_bfloat16 g_w14b[(size_t)(2*FFN) * K2H];
__device__ __nv_bfloat16 g_w41b[(size_t)HID * K2F];
__device__ __nv_bfloat16 g_x2[(size_t)M_ROWS * K2H];
__device__ __nv_bfloat16 g_a2[(size_t)M_ROWS * K2H];
__device__ __nv_bfloat16 g_y2[(size_t)M_ROWS * K2H];
__device__ __nv_bfloat16 g_g2[(size_t)M_ROWS * K2F];

// ------------------------- PTX helpers -------------------------
__device__ __forceinline__ uint32_t smem_u32(const void* p) {
    uint32_t a;
    asm("{ .reg .u64 t; cvta.to.shared.u64 t, %1; cvt.u32.u64 %0, t; }" : "=r"(a) : "l"(p));
    return a;
}
__device__ __forceinline__ void cp16(uint32_t s, const void* g) {
    asm volatile("cp.async.cg.shared.global [%0], [%1], 16;" :: "r"(s), "l"(g));
}
__device__ __forceinline__ void ldsm4(uint32_t* r, uint32_t addr) {
    asm volatile("ldmatrix.sync.aligned.m8n8.x4.shared.b16 {%0,%1,%2,%3}, [%4];"
                 : "=r"(r[0]), "=r"(r[1]), "=r"(r[2]), "=r"(r[3]) : "r"(addr));
}
__device__ __forceinline__ void mma16816(float* c, const uint32_t* a, uint32_t b0, uint32_t b1) {
    asm volatile(
        "mma.sync.aligned.m16n8k16.row.col.f32.bf16.bf16.f32 "
        "{%0,%1,%2,%3}, {%4,%5,%6,%7}, {%8,%9}, {%0,%1,%2,%3};"
        : "+f"(c[0]), "+f"(c[1]), "+f"(c[2]), "+f"(c[3])
        : "r"(a[0]), "r"(a[1]), "r"(a[2]), "r"(a[3]), "r"(b0), "r"(b1));
}

// ------------------------- misc helpers -------------------------
__device__ __forceinline__ float warp_sum(float v) {
#pragma unroll
    for (int o = 16; o > 0; o >>= 1) v += __shfl_xor_sync(0xffffffffu, v, o);
    return v;
}
__device__ __forceinline__ void split4p(float4 v, uint2& hi, uint2& lo) {
    union { uint2 u; __nv_bfloat16 h[4]; } H, L;
    float f[4] = {v.x, v.y, v.z, v.w};
#pragma unroll
    for (int k = 0; k < 4; k++) {
        __nv_bfloat16 h = __float2bfloat16(f[k]);
        H.h[k] = h;
        L.h[k] = __float2bfloat16(f[k] - __bfloat162float(h));
    }
    hi = H.u; lo = L.u;
}

// ------------------------- fp32 -> planar split-bf16 (weights) -------------------------
__global__ void split_planar_kernel(const float* __restrict__ in,
                                    __nv_bfloat16* __restrict__ out,
                                    long long n4, int kq) {
    long long i = (long long)blockIdx.x * blockDim.x + threadIdx.x;
    if (i >= n4) return;
    float4 v = ((const float4*)in)[i];
    uint2 hi, lo;
    split4p(v, hi, lo);
    long long n = i / kq;
    long long hidx = i + n * kq;
    ((uint2*)out)[hidx] = hi;
    ((uint2*)out)[hidx + kq] = lo;
}

// ------------------------- fused (add+)rmsnorm, planar split output -------------------------
__global__ void __launch_bounds__(256) fused_norm_kernel(
    const float* __restrict__ res, const float* __restrict__ x,
    const float* __restrict__ w, float* __restrict__ hid_out,
    __nv_bfloat16* __restrict__ y2) {
    __shared__ __align__(16) float buf[HID];
    __shared__ float red[8];
    int row = blockIdx.x;
    size_t base = (size_t)row * HID;
    const float4* x4 = (const float4*)(x + base);
    const float4* r4 = res ? (const float4*)(res + base) : nullptr;
    float4* b4 = (float4*)buf;

    float ss = 0.f;
    for (int i = threadIdx.x; i < HID/4; i += 256) {
        float4 v = x4[i];
        if (r4) { float4 rr = r4[i]; v.x += rr.x; v.y += rr.y; v.z += rr.z; v.w += rr.w; }
        b4[i] = v;
        ss += v.x*v.x + v.y*v.y + v.z*v.z + v.w*v.w;
    }
    ss = warp_sum(ss);
    if ((threadIdx.x & 31) == 0) red[threadIdx.x >> 5] = ss;
    __syncthreads();
    float tot = 0.f;
#pragma unroll
    for (int i = 0; i < 8; i++) tot += red[i];
    float inv = rsqrtf(tot / (float)HID + EPSV);

    uint2* yh = (uint2*)(y2 + (size_t)row * K2H);
    uint2* yl = (uint2*)(y2 + (size_t)row * K2H + HID);
    float4* h4 = hid_out ? (float4*)(hid_out + base) : nullptr;
    const float4* w4 = (const float4*)w;
    for (int i = threadIdx.x; i < HID/4; i += 256) {
        float4 v = b4[i];
        if (h4) h4[i] = v;
        float4 ww = w4[i];
        float4 o;
        o.x = v.x * inv * ww.x; o.y = v.y * inv * ww.y;
        o.z = v.z * inv * ww.z; o.w = v.w * inv * ww.w;
        uint2 hi, lo;
        split4p(o, hi, lo);
        yh[i] = hi; yl[i] = lo;
    }
}

// ------------------------- split-bf16 HMMA GEMM -------------------------
// C[M=2048, N] = A * B^T where A2[M,2K]=[hi|lo], B2[N,2K]=[hi|lo].
// 3 K-phases: hiA*hiB, hiA*loB, loA*hiB. Tile 128x128, chunk 64 elems.
// 3-stage cp.async pipeline, ONE __syncthreads per iteration (loads issued
// post-barrier -> WAR hazard on stage (i-1)%3 is barrier-protected).
// 2 CTAs/SM (2*97KB smem, <=128 regs).
#define NSTAGE 3
#define STAGE_BYTES 32768
#define GEMM_SMEM (NSTAGE * STAGE_BYTES + 1024)

__global__ void __launch_bounds__(256, 2) gemm_bf16(
    const __nv_bfloat16* __restrict__ A, const __nv_bfloat16* __restrict__ B,
    const float* __restrict__ bias, const float* __restrict__ resid,
    float* __restrict__ C, int NT, int Kel, int N) {
    extern __shared__ char smem[];
    uint32_t dataA = (smem_u32(smem) + 1023) & ~1023u;
    int tid = threadIdx.x;
    int wid = tid >> 5, lane = tid & 31;

    // supertile rasterization: 16 m-tiles x 18 n-tiles
    int g = blockIdx.x / (16*18);
    int r = blockIdx.x % (16*18);
    int gn = NT - g*18; if (gn > 18) gn = 18;
    int bn = (g*18 + r % gn) * 128;
    int bm = (r / gn) * 128;

    const size_t rowb = (size_t)Kel * 4;   // bytes per planar row (2K bf16)
    const char* Abase = (const char*)A + (size_t)bm * rowb;
    const char* Bbase = (const char*)B + (size_t)bn * rowb;
    const int KC = Kel >> 6;
    const int NC = 3 * KC;
    const int c16 = (tid & 7) * 16;
    const int row0 = tid >> 3;

    auto load_chunk = [&](int j) {
        int phase = (j >= 2*KC) ? 2 : (j >= KC ? 1 : 0);
        int jj = j - phase*KC;
        size_t a_byte = ((size_t)(phase == 2 ? Kel : 0) + (size_t)jj*64) * 2 + c16;
        size_t b_byte = ((size_t)(phase == 1 ? Kel : 0) + (size_t)jj*64) * 2 + c16;
        int s = j % NSTAGE;
        uint32_t sA = dataA + s*STAGE_BYTES;
        uint32_t sB = sA + 16384;
#pragma unroll
        for (int p = 0; p < 4; p++) {
            int row = row0 + p*32;
            uint32_t sw = row*128 + (c16 ^ ((row & 7) << 4));
            cp16(sA + sw, Abase + (size_t)row * rowb + a_byte);
            cp16(sB + sw, Bbase + (size_t)row * rowb + b_byte);
        }
        asm volatile("cp.async.commit_group;" ::: "memory");
    };

    float acc[4][4][4];
#pragma unroll
    for (int a = 0; a < 4; a++)
#pragma unroll
        for (int b = 0; b < 4; b++)
#pragma unroll
            for (int c = 0; c < 4; c++) acc[a][b][c] = 0.f;

    const int warp_m = (wid & 1) * 64;
    const int warp_n = (wid >> 1) * 32;

    load_chunk(0);
    load_chunk(1);

    for (int i = 0; i < NC; i++) {
        asm volatile("cp.async.wait_group 1;" ::: "memory");
        __syncthreads();

        uint32_t sA = dataA + (i % NSTAGE)*STAGE_BYTES;
        uint32_t sB = sA + 16384;
#pragma unroll
        for (int ks = 0; ks < 4; ks++) {
            int kb = ks * 32;
            uint32_t af[4][4];
#pragma unroll
            for (int mt = 0; mt < 4; mt++) {
                int rw = warp_m + mt*16 + (lane & 15);
                int cb = kb + ((lane >> 4) << 4);
                ldsm4(af[mt], sA + rw*128 + (cb ^ ((rw & 7) << 4)));
            }
            uint32_t bf[2][4];
#pragma unroll
            for (int nt = 0; nt < 2; nt++) {
                int nr = warp_n + nt*16 + ((lane >> 4) << 3) + (lane & 7);
                int cb = kb + (((lane >> 3) & 1) << 4);
                ldsm4(bf[nt], sB + nr*128 + (cb ^ ((nr & 7) << 4)));
            }
#pragma unroll
            for (int mt = 0; mt < 4; mt++) {
#pragma unroll
                for (int nj = 0; nj < 4; nj++) {
                    const uint32_t* bb = bf[nj >> 1];
                    uint32_t b0 = (nj & 1) ? bb[2] : bb[0];
                    uint32_t b1 = (nj & 1) ? bb[3] : bb[1];
                    mma16816(acc[mt][nj], af[mt], b0, b1);
                }
            }
        }
        // issue next stage AFTER the barrier: writes stage (i-1)%3, whose
        // compute finished (by ALL threads) before this iteration's barrier.
        if (i + 2 < NC) load_chunk(i + 2);
        else asm volatile("cp.async.commit_group;" ::: "memory");
    }

    // epilogue (optional bias over columns, optional residual add)
#pragma unroll
    for (int mt = 0; mt < 4; mt++) {
        int row0g = bm + warp_m + mt*16 + (lane >> 2);
#pragma unroll
        for (int nj = 0; nj < 4; nj++) {
            int col = bn + warp_n + nj*8 + (lane & 3)*2;
            float b0 = 0.f, b1 = 0.f;
            if (bias) { b0 = bias[col]; b1 = bias[col+1]; }
            float* p0 = C + (size_t)row0g * N + col;
            float* p1 = C + (size_t)(row0g + 8) * N + col;
            float2 v0 = make_float2(acc[mt][nj][0] + b0, acc[mt][nj][1] + b1);
            float2 v1 = make_float2(acc[mt][nj][2] + b0, acc[mt][nj][3] + b1);
            if (resid) {
                float2 r0 = *(const float2*)(resid + (size_t)row0g * N + col);
                float2 r1 = *(const float2*)(resid + (size_t)(row0g + 8) * N + col);
                v0.x += r0.x; v0.y += r0.y; v1.x += r1.x; v1.y += r1.y;
            }
            *(float2*)p0 = v0;
            *(float2*)p1 = v1;
        }
    }
}

// ------------------------- RoPE (in-place on q,k of qkv) -------------------------
__global__ void rope_kernel(const int* __restrict__ positions, float* __restrict__ qkv) {
    int bs = blockIdx.x;
    int hh = blockIdx.y;
    int i  = threadIdx.x;
    float* base = qkv + (size_t)bs * QKV_DIM + hh * HD;
    float pos = (float)positions[bs];
    float freq = __expf(-(float)i * 0.14391565217f);
    float ang = pos * freq;
    float sn, cs;
    sincosf(ang, &sn, &cs);
    float x1 = base[i];
    float x2 = base[i + 64];
    base[i]      = x1 * cs - x2 * sn;
    base[i + 64] = x2 * cs + x1 * sn;
}

// ------------------------- flash attention (causal, GQA), planar split ctx out ----
__global__ void __launch_bounds__(128) flash_attn_kernel(
    const float* __restrict__ qkv, __nv_bfloat16* __restrict__ a2) {
    __shared__ __align__(16) float Qs[32][HD];
    __shared__ __align__(16) float KVs[32][HD];
    __shared__ float Ss[32][33];
    __shared__ float m_s[32], l_s[32], alpha_s[32];

    int qt = blockIdx.x;
    int h  = blockIdx.y;
    int b  = blockIdx.z;
    int kvh = h >> 4;
    int tid = threadIdx.x;
    int r  = tid >> 2;
    int qd = tid & 3;
    int q0 = qt * 32;

    for (int i = tid; i < 32*32; i += 128) {
        int row = i >> 5, c4 = i & 31;
        ((float4*)Qs[row])[c4] =
            *(const float4*)(qkv + (size_t)(b*SEQ + q0 + row) * QKV_DIM + h*HD + c4*4);
    }
    if (tid < 32) { m_s[tid] = -1e30f; l_s[tid] = 0.f; }
    float acc[32];
#pragma unroll
    for (int i = 0; i < 32; i++) acc[i] = 0.f;
    __syncthreads();

    const float scale = 0.08838834764831845f;

    for (int kt = 0; kt <= qt; kt++) {
        int k0 = kt * 32;
        for (int i = tid; i < 32*32; i += 128) {
            int row = i >> 5, c4 = i & 31;
            ((float4*)KVs[row])[c4] =
                *(const float4*)(qkv + (size_t)(b*SEQ + k0 + row) * QKV_DIM + K_OFF + kvh*HD + c4*4);
        }
        __syncthreads();

        int j0 = qd * 8;
        float sc[8];
#pragma unroll
        for (int jj = 0; jj < 8; jj++) sc[jj] = 0.f;
        const float4* q4 = (const float4*)Qs[r];
#pragma unroll 4
        for (int d4 = 0; d4 < 32; d4++) {
            float4 qv = q4[d4];
#pragma unroll
            for (int jj = 0; jj < 8; jj++) {
                float4 kv = ((const float4*)KVs[j0 + jj])[d4];
                sc[jj] += qv.x*kv.x + qv.y*kv.y + qv.z*kv.z + qv.w*kv.w;
            }
        }
#pragma unroll
        for (int jj = 0; jj < 8; jj++) {
            int kg = k0 + j0 + jj;
            Ss[r][j0 + jj] = (kg <= q0 + r) ? sc[jj] * scale : -1e30f;
        }
        __syncthreads();

        if (tid < 32) {
            float mx = m_s[tid];
            float tm = -1e30f;
#pragma unroll 8
            for (int j = 0; j < 32; j++) tm = fmaxf(tm, Ss[tid][j]);
            float mn = fmaxf(mx, tm);
            float al = __expf(mx - mn);
            float sum = 0.f;
#pragma unroll 8
            for (int j = 0; j < 32; j++) {
                float p = __expf(Ss[tid][j] - mn);
                Ss[tid][j] = p;
                sum += p;
            }
            m_s[tid] = mn;
            l_s[tid] = l_s[tid] * al + sum;
            alpha_s[tid] = al;
        }
        for (int i = tid; i < 32*32; i += 128) {
            int row = i >> 5, c4 = i & 31;
            ((float4*)KVs[row])[c4] =
                *(const float4*)(qkv + (size_t)(b*SEQ + k0 + row) * QKV_DIM + V_OFF + kvh*HD + c4*4);
        }
        __syncthreads();

        float al = alpha_s[r];
#pragma unroll
        for (int i = 0; i < 32; i++) acc[i] *= al;
#pragma unroll 4
        for (int j = 0; j < 32; j++) {
            float p = Ss[r][j];
            const float4* v4 = (const float4*)&KVs[j][qd*32];
#pragma unroll
            for (int i4 = 0; i4 < 8; i4++) {
                float4 vv = v4[i4];
                acc[i4*4+0] = fmaf(p, vv.x, acc[i4*4+0]);
                acc[i4*4+1] = fmaf(p, vv.y, acc[i4*4+1]);
                acc[i4*4+2] = fmaf(p, vv.z, acc[i4*4+2]);
                acc[i4*4+3] = fmaf(p, vv.w, acc[i4*4+3]);
            }
        }
        __syncthreads();
    }

    float invl = 1.f / l_s[r];
    size_t rbase = (size_t)(b*SEQ + q0 + r) * K2H;
    uint2* oh = (uint2*)(a2 + rbase + h*HD + qd*32);
    uint2* ol = (uint2*)(a2 + rbase + HID + h*HD + qd*32);
#pragma unroll
    for (int i4 = 0; i4 < 8; i4++) {
        float4 o = make_float4(acc[i4*4+0]*invl, acc[i4*4+1]*invl,
                               acc[i4*4+2]*invl, acc[i4*4+3]*invl);
        uint2 hi, lo;
        split4p(o, hi, lo);
        oh[i4] = hi; ol[i4] = lo;
    }
}

// ------------------------- SwiGLU + planar split -------------------------
__global__ void swiglu_split_kernel(const float* __restrict__ inter,
                                    __nv_bfloat16* __restrict__ g2) {
    int t = blockIdx.x * blockDim.x + threadIdx.x;
    if (t >= M_ROWS * (FFN/4)) return;
    int row = t / (FFN/4);
    int f4  = t - row * (FFN/4);
    const float* irow = inter + (size_t)row * (2*FFN);
    float4 a = *(const float4*)(irow + f4*4);
    float4 b = *(const float4*)(irow + FFN + f4*4);
    float4 o;
    o.x = (a.x / (1.f + __expf(-a.x))) * b.x;
    o.y = (a.y / (1.f + __expf(-a.y))) * b.y;
    o.z = (a.z / (1.f + __expf(-a.z))) * b.z;
    o.w = (a.w / (1.f + __expf(-a.w))) * b.w;
    uint2 hi, lo;
    split4p(o, hi, lo);
    size_t rbase = (size_t)row * K2F;
    *(uint2*)(g2 + rbase + f4*4) = hi;
    *(uint2*)(g2 + rbase + FFN + f4*4) = lo;
}

// ------------------------- launch -------------------------
extern "C" void kernel_launch(void* const* d_in, const int* in_sizes, int n_in,
                              void* d_out, int out_size) {
    const int*   positions = (const int*)d_in[0];
    const float* hs        = (const float*)d_in[1];
    const float* ln1       = (const float*)d_in[2];
    const float* wqkv      = (const float*)d_in[3];
    const float* bqkv      = (const float*)d_in[4];
    const float* wo        = (const float*)d_in[5];
    const float* ln2       = (const float*)d_in[6];
    const float* w14       = (const float*)d_in[7];
    const float* w41       = (const float*)d_in[8];
    float* out = (float*)d_out;

    float *qkv, *attnout, *hidden, *inter;
    __nv_bfloat16 *wqkv2, *wo2, *w14b, *w41b, *x2, *a2, *y2, *g2;
    cudaGetSymbolAddress((void**)&qkv,     g_qkv);
    cudaGetSymbolAddress((void**)&attnout, g_attnout);
    cudaGetSymbolAddress((void**)&hidden,  g_hidden);
    cudaGetSymbolAddress((void**)&inter,   g_inter);
    cudaGetSymbolAddress((void**)&wqkv2,   g_wqkv2);
    cudaGetSymbolAddress((void**)&wo2,     g_wo2);
    cudaGetSymbolAddress((void**)&w14b,    g_w14b);
    cudaGetSymbolAddress((void**)&w41b,    g_w41b);
    cudaGetSymbolAddress((void**)&x2,      g_x2);
    cudaGetSymbolAddress((void**)&a2,      g_a2);
    cudaGetSymbolAddress((void**)&y2,      g_y2);
    cudaGetSymbolAddress((void**)&g2,      g_g2);

    cudaFuncSetAttribute(gemm_bf16, cudaFuncAttributeMaxDynamicSharedMemorySize, GEMM_SMEM);

    // weight splits (planar)
    {
        long long n4;
        n4 = (long long)QKV_DIM * HID / 4;
        split_planar_kernel<<<(unsigned)((n4+255)/256), 256>>>(wqkv, wqkv2, n4, HID/4);
        n4 = (long long)HID * HID / 4;
        split_planar_kernel<<<(unsigned)((n4+255)/256), 256>>>(wo, wo2, n4, HID/4);
        n4 = (long long)(2*FFN) * HID / 4;
        split_planar_kernel<<<(unsigned)((n4+255)/256), 256>>>(w14, w14b, n4, HID/4);
        n4 = (long long)HID * FFN / 4;
        split_planar_kernel<<<(unsigned)((n4+255)/256), 256>>>(w41, w41b, n4, FFN/4);
    }

    // 1) x2 = split(rmsnorm(hs) * ln1)
    fused_norm_kernel<<<M_ROWS, 256>>>(nullptr, hs, ln1, nullptr, x2);

    // 2) qkv = x @ wqkv^T + bqkv
    gemm_bf16<<<16*36, 256, GEMM_SMEM>>>(x2, wqkv2, bqkv, nullptr, qkv, 36, HID, QKV_DIM);

    // 3) rope on q,k
    rope_kernel<<<dim3(M_ROWS, NH + NKV), 64>>>(positions, qkv);

    // 4) attention -> a2 (planar split ctx)
    flash_attn_kernel<<<dim3(SEQ/32, NH, BATCH), 128>>>(qkv, a2);

    // 5) attn_out = ctx @ wo^T
    gemm_bf16<<<16*32, 256, GEMM_SMEM>>>(a2, wo2, nullptr, nullptr, attnout, 32, HID, HID);

    // 6) hidden = hs + attn_out ; y2 = split(rmsnorm(hidden) * ln2)
    fused_norm_kernel<<<M_ROWS, 256>>>(hs, attnout, ln2, hidden, y2);

    // 7) inter = y @ w14^T
    gemm_bf16<<<16*214, 256, GEMM_SMEM>>>(y2, w14b, nullptr, nullptr, inter, 214, HID, 2*FFN);

    // 8) g2 = split(silu(a)*b)
    swiglu_split_kernel<<<(M_ROWS*(FFN/4) + 255)/256, 256>>>(inter, g2);

    // 9) out = hidden + gated @ w41^T   (residual fused into epilogue)
    gemm_bf16<<<16*32, 256, GEMM_SMEM>>>(g2, w41b, nullptr, hidden, out, 32, FFN, HID);
}